// round 15
// baseline (speedup 1.0000x reference)
#include <cuda_runtime.h>
#include <cuda_bf16.h>
#include <math.h>

// ---------------- constants ----------------
#define RES   56
#define WS    7
#define SHIFT 3
#define DIM   192
#define HEADS 6
#define HD    32
#define NTOK  49
#define BATCH 32
#define NWIN  64
#define BW    (BATCH*NWIN)        // 2048 windows
#define TTOK  (BW*NTOK)           // 100352 rows
#define SCALE 0.17677669529663687f

#define W_QKV_N    (DIM*3*DIM)
#define W_PROJ_N   (DIM*DIM)
#define W_FC1_N    (DIM*4*DIM)
#define W_FC2_N    (4*DIM*DIM)
#define W_TOTAL    (W_QKV_N + W_PROJ_N + W_FC1_N + W_FC2_N)
// word (bf16-pair) offsets ([K/2][N] layout per matrix)
#define WW_QKV_OFF  0
#define WW_PROJ_OFF (WW_QKV_OFF + W_QKV_N/2)
#define WW_FC1_OFF  (WW_PROJ_OFF + W_PROJ_N/2)
#define WW_FC2_OFF  (WW_FC1_OFF + W_FC1_N/2)
#define WW_TOTAL    (W_TOTAL/2)

// ---------------- scratch ----------------
__device__ __nv_bfloat16 g_hln[TTOK*DIM];
__device__ __nv_bfloat16 g_q  [TTOK*DIM];
__device__ __nv_bfloat16 g_k  [TTOK*DIM];
__device__ __nv_bfloat16 g_v  [TTOK*DIM];
__device__ __nv_bfloat16 g_ao [TTOK*DIM];
__device__ float         g_xn [TTOK*DIM];
__device__ __nv_bfloat16 g_ml [TTOK*4*DIM];
__device__ unsigned      g_wh [WW_TOTAL];
__device__ float         g_bt [4*HEADS*NTOK*NTOK];

__device__ __forceinline__ int win_src_token(int m) {
    int win = m / NTOK, n = m - win * NTOK;
    int b   = win >> 6, wi = win & 63;
    int wy  = wi >> 3,  wx = wi & 7;
    int py  = n / WS,   px = n - py * WS;
    int y = wy * WS + py + SHIFT; if (y >= RES) y -= RES;
    int x = wx * WS + px + SHIFT; if (x >= RES) x -= RES;
    return b * (RES*RES) + y * RES + x;
}

// ---------------- weight prep: fp32 [K][N] -> bf16 pair words [K/2][N] ----------------
__global__ void round_w(const float* __restrict__ s0, const float* __restrict__ s1,
                        const float* __restrict__ s2, const float* __restrict__ s3) {
    int i = blockIdx.x * blockDim.x + threadIdx.x;
    if (i >= WW_TOTAL) return;
    const float* src; int nc, local;
    if (i < WW_PROJ_OFF)      { src = s0; nc = 3*DIM; local = i - WW_QKV_OFF; }
    else if (i < WW_FC1_OFF)  { src = s1; nc = DIM;   local = i - WW_PROJ_OFF; }
    else if (i < WW_FC2_OFF)  { src = s2; nc = 4*DIM; local = i - WW_FC1_OFF; }
    else                      { src = s3; nc = DIM;   local = i - WW_FC2_OFF; }
    int kp = local / nc, n = local - kp * nc;
    __nv_bfloat16 lo = __float2bfloat16_rn(src[(2*kp    ) * nc + n]);
    __nv_bfloat16 hi = __float2bfloat16_rn(src[(2*kp + 1) * nc + n]);
    g_wh[i] = ((unsigned)__bfloat16_as_ushort(hi) << 16) | __bfloat16_as_ushort(lo);
}

// ---------------- attention bias+mask precompute ----------------
__global__ void prep_bias(const float* __restrict__ btab) {
    int idx = blockIdx.x * 256 + threadIdx.x;
    if (idx >= 4*HEADS*NTOK*NTOK) return;
    int j = idx % NTOK; int r = idx / NTOK;
    int i = r % NTOK;   r /= NTOK;
    int head = r % HEADS;
    int cls  = r / HEADS;
    int cy = cls >> 1, cx = cls & 1;
    int yi = i / WS, xi = i - yi*WS;
    int yj = j / WS, xj = j - yj*WS;
    int rel = (yi - yj + WS - 1) * (2*WS - 1) + (xi - xj + WS - 1);
    float s = btab[rel * HEADS + head];
    int ryi = cy ? ((yi < WS - SHIFT) ? 1 : 2) : 0;
    int rxi = cx ? ((xi < WS - SHIFT) ? 1 : 2) : 0;
    int ryj = cy ? ((yj < WS - SHIFT) ? 1 : 2) : 0;
    int rxj = cx ? ((xj < WS - SHIFT) ? 1 : 2) : 0;
    if (ryi*3 + rxi != ryj*3 + rxj) s -= 100.f;
    g_bt[idx] = s;
}

// ---------------- LayerNorm (bf16 output), optional window-gather ----------------
template<int GATHER>
__global__ void ln_kernel(const float* __restrict__ src, const float* __restrict__ g,
                          const float* __restrict__ bta, __nv_bfloat16* __restrict__ dst) {
    int tok  = blockIdx.x * 8 + (threadIdx.x >> 5);
    int lane = threadIdx.x & 31;
    if (tok >= TTOK) return;
    int srow = GATHER ? win_src_token(tok) : tok;
    const float* p = src + (size_t)srow * DIM;
    float v[6];
    float s = 0.f;
#pragma unroll
    for (int j = 0; j < 6; j++) { v[j] = p[j*32 + lane]; s += v[j]; }
#pragma unroll
    for (int o = 16; o; o >>= 1) s += __shfl_xor_sync(0xffffffffu, s, o);
    float mu = s * (1.f / DIM);
    float vr = 0.f;
#pragma unroll
    for (int j = 0; j < 6; j++) { float d = v[j] - mu; vr += d * d; }
#pragma unroll
    for (int o = 16; o; o >>= 1) vr += __shfl_xor_sync(0xffffffffu, vr, o);
    float r = rsqrtf(vr * (1.f / DIM) + 1e-5f);
    __nv_bfloat16* q = dst + (size_t)tok * DIM;
#pragma unroll
    for (int j = 0; j < 6; j++) {
        int c = j*32 + lane;
        q[c] = __float2bfloat16_rn((v[j] - mu) * r * g[c] + bta[c]);
    }
}

// ---------------- MMA primitives ----------------
__device__ __forceinline__ void mma8(float* c, const unsigned* a, const unsigned* b) {
    asm volatile("mma.sync.aligned.m16n8k8.row.col.f32.tf32.tf32.f32 "
        "{%0,%1,%2,%3},{%4,%5,%6,%7},{%8,%9},{%0,%1,%2,%3};"
        : "+f"(c[0]), "+f"(c[1]), "+f"(c[2]), "+f"(c[3])
        : "r"(a[0]), "r"(a[1]), "r"(a[2]), "r"(a[3]), "r"(b[0]), "r"(b[1]));
}
__device__ __forceinline__ void mma16(float* c, const unsigned* a, const unsigned* b) {
    asm volatile("mma.sync.aligned.m16n8k16.row.col.f32.bf16.bf16.f32 "
        "{%0,%1,%2,%3},{%4,%5,%6,%7},{%8,%9},{%0,%1,%2,%3};"
        : "+f"(c[0]), "+f"(c[1]), "+f"(c[2]), "+f"(c[3])
        : "r"(a[0]), "r"(a[1]), "r"(a[2]), "r"(a[3]), "r"(b[0]), "r"(b[1]));
}

// ---------------- BF16 GEMM, cp.async 3-stage, K=32 per stage (this round's delta) ----
// smem word layouts per stage: A [256 rows][16 kp + 4 pad] stride 20 (20g mod 32 distinct);
//                              B [16 kp][64 n + 8 pad] stride 72.
#define AST2 20
#define BST  72
#define ASZ2 (256*AST2)   // 5120 words/stage
#define BSZ2 (16*BST)     // 1152 words/stage
#define SMEM_G (3*(ASZ2 + BSZ2)*4)   // 75264 bytes (dynamic)

template<int EPI, int K, int NC>
__global__ __launch_bounds__(256)
void gemm_tc(const __nv_bfloat16* __restrict__ A, const unsigned* __restrict__ Wp,
             const float* __restrict__ bias,
             const float* __restrict__ extra_in,
             float* __restrict__ out, float* __restrict__ out2, float* __restrict__ out3) {
    extern __shared__ unsigned sm[];
    unsigned* AsB = sm;                 // 3 stages of A
    unsigned* BsB = sm + 3*ASZ2;        // 3 stages of B

    int t    = threadIdx.x;
    int br   = blockIdx.y * 256;
    int bc   = blockIdx.x * 64;
    int lane = t & 31, warp = t >> 5;
    int wm   = warp & 3, wn = warp >> 2;
    int gid  = lane >> 2, tig = lane & 3;

    const __nv_bfloat16* aRow = A + (size_t)(br + t) * K;
    unsigned aDst = (unsigned)__cvta_generic_to_shared(&AsB[t * AST2]);
    int bk = t >> 4, bn4 = (t & 15) * 4;
    unsigned bDst = (unsigned)__cvta_generic_to_shared(&BsB[bk * BST + bn4]);

    float acc[4][4][4];
#pragma unroll
    for (int mt = 0; mt < 4; mt++)
#pragma unroll
        for (int nt = 0; nt < 4; nt++)
#pragma unroll
            for (int e = 0; e < 4; e++) acc[mt][nt][e] = 0.f;

    constexpr int KT = K >> 5;   // K32 stages

#define ISSUE(S, TI)                                                              \
    do {                                                                          \
        unsigned ad = aDst + (S) * (ASZ2 * 4);                                    \
        const __nv_bfloat16* ap = aRow + (TI) * 32;                               \
        asm volatile("cp.async.cg.shared.global [%0], [%1], 16;\n"                \
                     :: "r"(ad),      "l"(ap)      : "memory");                   \
        asm volatile("cp.async.cg.shared.global [%0], [%1], 16;\n"                \
                     :: "r"(ad + 16), "l"(ap + 8)  : "memory");                   \
        asm volatile("cp.async.cg.shared.global [%0], [%1], 16;\n"                \
                     :: "r"(ad + 32), "l"(ap + 16) : "memory");                   \
        asm volatile("cp.async.cg.shared.global [%0], [%1], 16;\n"                \
                     :: "r"(ad + 48), "l"(ap + 24) : "memory");                   \
        {                                                                         \
            const unsigned* bp = Wp + (size_t)((TI)*16 + bk) * NC + bc + bn4;     \
            asm volatile("cp.async.cg.shared.global [%0], [%1], 16;\n"            \
                         :: "r"(bDst + (S) * (BSZ2 * 4)), "l"(bp) : "memory");    \
        }                                                                         \
        asm volatile("cp.async.commit_group;\n" ::: "memory");                    \
    } while (0)

    ISSUE(0, 0);
    ISSUE(1, 1);

    for (int kt = 0; kt < KT; kt++) {
        if (kt < KT - 1) asm volatile("cp.async.wait_group 1;\n" ::: "memory");
        else             asm volatile("cp.async.wait_group 0;\n" ::: "memory");
        __syncthreads();
        int snext = kt + 2;
        if (snext < KT) {
            int sn = snext - (snext / 3) * 3;
            ISSUE(sn, snext);
        }
        int s = kt - (kt / 3) * 3;
        const unsigned* as = AsB + s * ASZ2;
        const unsigned* bs = BsB + s * BSZ2;

#pragma unroll
        for (int s16 = 0; s16 < 2; s16++) {
            int ko = s16 * 8;
            unsigned a[4][4], b[4][2];
#pragma unroll
            for (int mt = 0; mt < 4; mt++) {
                int rb = wm*64 + mt*16 + gid;
                a[mt][0] = as[ rb      * AST2 + ko + tig];
                a[mt][1] = as[(rb + 8) * AST2 + ko + tig];
                a[mt][2] = as[ rb      * AST2 + ko + tig + 4];
                a[mt][3] = as[(rb + 8) * AST2 + ko + tig + 4];
            }
#pragma unroll
            for (int nt = 0; nt < 4; nt++) {
                int cb = wn*32 + nt*8 + gid;
                b[nt][0] = bs[(ko + tig    ) * BST + cb];
                b[nt][1] = bs[(ko + tig + 4) * BST + cb];
            }
#pragma unroll
            for (int mt = 0; mt < 4; mt++)
#pragma unroll
                for (int nt = 0; nt < 4; nt++) mma16(acc[mt][nt], a[mt], b[nt]);
        }
    }
#undef ISSUE

    // epilogue (R14 verbatim)
#pragma unroll
    for (int mt = 0; mt < 4; mt++) {
#pragma unroll
        for (int rr = 0; rr < 2; rr++) {
            int row = br + wm*64 + mt*16 + gid + rr*8;
            int dst = 0, win = 0, n = 0;
            if (EPI == 0) { win = row / NTOK; n = row - win * NTOK; }
            if (EPI == 1) { dst = win_src_token(row); }
#pragma unroll
            for (int nt = 0; nt < 4; nt++) {
                if (EPI == 0) {
                    int col0 = bc + wn*32 + nt*8 + tig*2;
                    float v0 = acc[mt][nt][rr*2 + 0] + __ldg(&bias[col0]);
                    float v1 = acc[mt][nt][rr*2 + 1] + __ldg(&bias[col0 + 1]);
                    int sseg   = col0 / DIM;
                    int within = col0 % DIM;
                    int hh = within >> 5, d = within & 31;
                    size_t off = (((size_t)(win*HEADS + hh)) * NTOK + n) * HD + d;
                    if (sseg == 0) { v0 *= SCALE; v1 *= SCALE; }
                    __nv_bfloat16* ob = (sseg == 0) ? (__nv_bfloat16*)out
                                      : ((sseg == 1) ? (__nv_bfloat16*)out2
                                                     : (__nv_bfloat16*)out3);
                    __nv_bfloat162 pp = __floats2bfloat162_rn(v0, v1);
                    *(__nv_bfloat162*)(ob + off) = pp;
                } else {
#pragma unroll
                    for (int cc = 0; cc < 2; cc++) {
                        int col = bc + wn*32 + nt*8 + tig*2 + cc;
                        float val = acc[mt][nt][rr*2 + cc] + __ldg(&bias[col]);
                        if (EPI == 1) {
                            size_t off = (size_t)dst * DIM + col;
                            out[off] = extra_in[off] + val;
                        } else if (EPI == 2) {
                            float ge = 0.5f * val * (1.f + erff(val * 0.70710678118654752f));
                            ((__nv_bfloat16*)out)[(size_t)row * (4*DIM) + col] =
                                __float2bfloat16_rn(ge);
                        } else {
                            size_t off = (size_t)row * DIM + col;
                            out[off] = val + extra_in[off];
                        }
                    }
                }
            }
        }
    }
}

// ---------------- attention (R14 verbatim) ----------------
__global__ __launch_bounds__(128, 6)
void attn_kernel() {
    int bh   = blockIdx.x;
    int win  = bh / HEADS;
    int head = bh - win * HEADS;

    __shared__ float qs [64][36];
    __shared__ float ksm[56][36];
    __shared__ float vsm[56][40];

    const unsigned* qp32 = (const unsigned*)(g_q + (size_t)bh * (NTOK*HD));
    const unsigned* kp32 = (const unsigned*)(g_k + (size_t)bh * (NTOK*HD));
    const unsigned* vp32 = (const unsigned*)(g_v + (size_t)bh * (NTOK*HD));

    int t = threadIdx.x;
    if (t < 224) vsm[NTOK + (t >> 5)][t & 31] = 0.f;
    for (int i = t; i < NTOK*16; i += 128) {
        int r = i >> 4, c2 = (i & 15) * 2;
        float2 fq = __bfloat1622float2(*(const __nv_bfloat162*)&qp32[i]);
        float2 fk = __bfloat1622float2(*(const __nv_bfloat162*)&kp32[i]);
        float2 fv = __bfloat1622float2(*(const __nv_bfloat162*)&vp32[i]);
        qs [r][c2] = fq.x; qs [r][c2 + 1] = fq.y;
        ksm[r][c2] = fk.x; ksm[r][c2 + 1] = fk.y;
        vsm[r][c2] = fv.x; vsm[r][c2 + 1] = fv.y;
    }
    __syncthreads();

    int lane = t & 31, warp = t >> 5;
    int gid  = lane >> 2, tig = lane & 3;
    int row0 = warp * 16 + gid;
    int row_lo = row0, row_hi = row0 + 8;

    float acc[7][4];
#pragma unroll
    for (int nt = 0; nt < 7; nt++)
#pragma unroll
        for (int e = 0; e < 4; e++) acc[nt][e] = 0.f;

#pragma unroll
    for (int k8 = 0; k8 < 4; k8++) {
        int kk = k8*8 + tig;
        unsigned a[4];
        a[0] = __float_as_uint(qs[row_lo][kk    ]);
        a[1] = __float_as_uint(qs[row_hi][kk    ]);
        a[2] = __float_as_uint(qs[row_lo][kk + 4]);
        a[3] = __float_as_uint(qs[row_hi][kk + 4]);
#pragma unroll
        for (int nt = 0; nt < 7; nt++) {
            unsigned b[2];
            b[0] = __float_as_uint(ksm[nt*8 + gid][kk    ]);
            b[1] = __float_as_uint(ksm[nt*8 + gid][kk + 4]);
            mma8(acc[nt], a, b);
        }
    }

    int wi = win & 63;
    int cls = (((wi >> 3) == 7) ? 2 : 0) | (((wi & 7) == 7) ? 1 : 0);
    const float* tb = g_bt + ((size_t)(cls * HEADS + head)) * (NTOK*NTOK);
#pragma unroll
    for (int nt = 0; nt < 7; nt++) {
#pragma unroll
        for (int e = 0; e < 4; e++) {
            int i = (e >= 2) ? row_hi : row_lo;
            int j = nt*8 + tig*2 + (e & 1);
            if (i < NTOK && j < NTOK)
                acc[nt][e] += __ldg(&tb[i * NTOK + j]);
            else
                acc[nt][e] = -1e30f;
        }
    }

    float m0 = -1e30f, m1 = -1e30f;
#pragma unroll
    for (int nt = 0; nt < 7; nt++) {
        m0 = fmaxf(m0, fmaxf(acc[nt][0], acc[nt][1]));
        m1 = fmaxf(m1, fmaxf(acc[nt][2], acc[nt][3]));
    }
    m0 = fmaxf(m0, __shfl_xor_sync(0xffffffffu, m0, 1));
    m0 = fmaxf(m0, __shfl_xor_sync(0xffffffffu, m0, 2));
    m1 = fmaxf(m1, __shfl_xor_sync(0xffffffffu, m1, 1));
    m1 = fmaxf(m1, __shfl_xor_sync(0xffffffffu, m1, 2));
    float s0 = 0.f, s1 = 0.f;
#pragma unroll
    for (int nt = 0; nt < 7; nt++) {
        acc[nt][0] = __expf(acc[nt][0] - m0); s0 += acc[nt][0];
        acc[nt][1] = __expf(acc[nt][1] - m0); s0 += acc[nt][1];
        acc[nt][2] = __expf(acc[nt][2] - m1); s1 += acc[nt][2];
        acc[nt][3] = __expf(acc[nt][3] - m1); s1 += acc[nt][3];
    }
    s0 += __shfl_xor_sync(0xffffffffu, s0, 1);
    s0 += __shfl_xor_sync(0xffffffffu, s0, 2);
    s1 += __shfl_xor_sync(0xffffffffu, s1, 1);
    s1 += __shfl_xor_sync(0xffffffffu, s1, 2);
    float inv0 = 1.f / s0, inv1 = 1.f / s1;
#pragma unroll
    for (int nt = 0; nt < 7; nt++) {
        acc[nt][0] *= inv0; acc[nt][1] *= inv0;
        acc[nt][2] *= inv1; acc[nt][3] *= inv1;
    }

    float oacc[4][4];
#pragma unroll
    for (int nt = 0; nt < 4; nt++)
#pragma unroll
        for (int e = 0; e < 4; e++) oacc[nt][e] = 0.f;

    int base = lane & ~3;
    int sl0  = base + (tig >> 1);
    int sl1  = sl0 + 2;
    int odd  = tig & 1;

#pragma unroll
    for (int k7 = 0; k7 < 7; k7++) {
        float x0 = acc[k7][0], x1 = acc[k7][1];
        float y0 = acc[k7][2], y1 = acc[k7][3];
        float t0, t1;
        unsigned a[4];
        t0 = __shfl_sync(0xffffffffu, x0, sl0);
        t1 = __shfl_sync(0xffffffffu, x1, sl0);
        a[0] = __float_as_uint(odd ? t1 : t0);
        t0 = __shfl_sync(0xffffffffu, y0, sl0);
        t1 = __shfl_sync(0xffffffffu, y1, sl0);
        a[1] = __float_as_uint(odd ? t1 : t0);
        t0 = __shfl_sync(0xffffffffu, x0, sl1);
        t1 = __shfl_sync(0xffffffffu, x1, sl1);
        a[2] = __float_as_uint(odd ? t1 : t0);
        t0 = __shfl_sync(0xffffffffu, y0, sl1);
        t1 = __shfl_sync(0xffffffffu, y1, sl1);
        a[3] = __float_as_uint(odd ? t1 : t0);

        int kk = k7*8 + tig;
#pragma unroll
        for (int nt = 0; nt < 4; nt++) {
            unsigned b[2];
            b[0] = __float_as_uint(vsm[kk    ][nt*8 + gid]);
            b[1] = __float_as_uint(vsm[kk + 4][nt*8 + gid]);
            mma8(oacc[nt], a, b);
        }
    }

    __nv_bfloat16* op = g_ao + ((size_t)win * NTOK) * DIM + head * HD;
#pragma unroll
    for (int nt = 0; nt < 4; nt++) {
#pragma unroll
        for (int e = 0; e < 4; e++) {
            int i = (e >= 2) ? row_hi : row_lo;
            int d = nt*8 + tig*2 + (e & 1);
            if (i < NTOK) op[(size_t)i * DIM + d] = __float2bfloat16_rn(oacc[nt][e]);
        }
    }
}

// ---------------- launch ----------------
static void* sym_ptr_raw(const void* sym) {
    void* p = nullptr;
    cudaGetSymbolAddress(&p, sym);
    return p;
}

extern "C" void kernel_launch(void* const* d_in, const int* in_sizes, int n_in,
                              void* d_out, int out_size) {
    const float* x       = (const float*)d_in[0];
    const float* n1g     = (const float*)d_in[1];
    const float* n1b     = (const float*)d_in[2];
    const float* qkv_w   = (const float*)d_in[3];
    const float* qkv_b   = (const float*)d_in[4];
    const float* proj_w  = (const float*)d_in[5];
    const float* proj_b  = (const float*)d_in[6];
    const float* btab    = (const float*)d_in[7];
    const float* n2g     = (const float*)d_in[8];
    const float* n2b     = (const float*)d_in[9];
    const float* fc1_w   = (const float*)d_in[10];
    const float* fc1_b   = (const float*)d_in[11];
    const float* fc2_w   = (const float*)d_in[12];
    const float* fc2_b   = (const float*)d_in[13];
    float* outp = (float*)d_out;

    __nv_bfloat16* hln = (__nv_bfloat16*)sym_ptr_raw(g_hln);
    __nv_bfloat16* q   = (__nv_bfloat16*)sym_ptr_raw(g_q);
    __nv_bfloat16* k   = (__nv_bfloat16*)sym_ptr_raw(g_k);
    __nv_bfloat16* v   = (__nv_bfloat16*)sym_ptr_raw(g_v);
    __nv_bfloat16* ao  = (__nv_bfloat16*)sym_ptr_raw(g_ao);
    float*         xn  = (float*)sym_ptr_raw(g_xn);
    __nv_bfloat16* ml  = (__nv_bfloat16*)sym_ptr_raw(g_ml);
    unsigned*      wh  = (unsigned*)sym_ptr_raw(g_wh);

    cudaFuncSetAttribute(gemm_tc<0, DIM,   3*DIM>, cudaFuncAttributeMaxDynamicSharedMemorySize, SMEM_G);
    cudaFuncSetAttribute(gemm_tc<1, DIM,   DIM  >, cudaFuncAttributeMaxDynamicSharedMemorySize, SMEM_G);
    cudaFuncSetAttribute(gemm_tc<2, DIM,   4*DIM>, cudaFuncAttributeMaxDynamicSharedMemorySize, SMEM_G);
    cudaFuncSetAttribute(gemm_tc<3, 4*DIM, DIM  >, cudaFuncAttributeMaxDynamicSharedMemorySize, SMEM_G);

    // 0. prep
    round_w<<<(WW_TOTAL + 255)/256, 256>>>(qkv_w, proj_w, fc1_w, fc2_w);
    prep_bias<<<(4*HEADS*NTOK*NTOK + 255)/256, 256>>>(btab);
    // 1. LN1 + roll + window partition (bf16)
    ln_kernel<1><<<TTOK/8, 256>>>(x, n1g, n1b, hln);
    // 2. qkv GEMM (bf16 out, paired stores)
    gemm_tc<0, DIM, 3*DIM><<<dim3((3*DIM)/64, TTOK/256), 256, SMEM_G>>>(hln, wh + WW_QKV_OFF, qkv_b,
                                                                        nullptr, (float*)q, (float*)k, (float*)v);
    // 3. windowed attention
    attn_kernel<<<BW*HEADS, 128>>>();
    // 4. proj GEMM + reverse scatter + residual
    gemm_tc<1, DIM, DIM><<<dim3(DIM/64, TTOK/256), 256, SMEM_G>>>(ao, wh + WW_PROJ_OFF, proj_b,
                                                                  x, xn, nullptr, nullptr);
    // 5. LN2 (bf16 out)
    ln_kernel<0><<<TTOK/8, 256>>>(xn, n2g, n2b, hln);
    // 6. fc1 GEMM + gelu (bf16 out)
    gemm_tc<2, DIM, 4*DIM><<<dim3((4*DIM)/64, TTOK/256), 256, SMEM_G>>>(hln, wh + WW_FC1_OFF, fc1_b,
                                                                        nullptr, (float*)ml, nullptr, nullptr);
    // 7. fc2 GEMM + residual -> output
    gemm_tc<3, 4*DIM, DIM><<<dim3(DIM/64, TTOK/256), 256, SMEM_G>>>(ml, wh + WW_FC2_OFF, fc2_b,
                                                                    xn, outp, nullptr, nullptr);
}

// round 16
// speedup vs baseline: 1.2169x; 1.2169x over previous
#include <cuda_runtime.h>
#include <cuda_bf16.h>
#include <math.h>

// ---------------- constants ----------------
#define RES   56
#define WS    7
#define SHIFT 3
#define DIM   192
#define HEADS 6
#define HD    32
#define NTOK  49
#define BATCH 32
#define NWIN  64
#define BW    (BATCH*NWIN)        // 2048 windows
#define TTOK  (BW*NTOK)           // 100352 rows
#define SCALE 0.17677669529663687f

#define W_QKV_N    (DIM*3*DIM)
#define W_PROJ_N   (DIM*DIM)
#define W_FC1_N    (DIM*4*DIM)
#define W_FC2_N    (4*DIM*DIM)
#define W_TOTAL    (W_QKV_N + W_PROJ_N + W_FC1_N + W_FC2_N)
// word (bf16-pair) offsets ([K/2][N] layout per matrix)
#define WW_QKV_OFF  0
#define WW_PROJ_OFF (WW_QKV_OFF + W_QKV_N/2)
#define WW_FC1_OFF  (WW_PROJ_OFF + W_PROJ_N/2)
#define WW_FC2_OFF  (WW_FC1_OFF + W_FC1_N/2)
#define WW_TOTAL    (W_TOTAL/2)

// ---------------- scratch ----------------
__device__ __nv_bfloat16 g_hln[TTOK*DIM];
__device__ __nv_bfloat16 g_q  [TTOK*DIM];
__device__ __nv_bfloat16 g_k  [TTOK*DIM];
__device__ __nv_bfloat16 g_v  [TTOK*DIM];
__device__ __nv_bfloat16 g_ao [TTOK*DIM];
__device__ float         g_xn [TTOK*DIM];
__device__ __nv_bfloat16 g_ml [TTOK*4*DIM];
__device__ unsigned      g_wh [WW_TOTAL];
__device__ float         g_bt [4*HEADS*NTOK*NTOK];

__device__ __forceinline__ int win_src_token(int m) {
    int win = m / NTOK, n = m - win * NTOK;
    int b   = win >> 6, wi = win & 63;
    int wy  = wi >> 3,  wx = wi & 7;
    int py  = n / WS,   px = n - py * WS;
    int y = wy * WS + py + SHIFT; if (y >= RES) y -= RES;
    int x = wx * WS + px + SHIFT; if (x >= RES) x -= RES;
    return b * (RES*RES) + y * RES + x;
}

// ---------------- weight prep: fp32 [K][N] -> bf16 pair words [K/2][N] ----------------
__global__ void round_w(const float* __restrict__ s0, const float* __restrict__ s1,
                        const float* __restrict__ s2, const float* __restrict__ s3) {
    int i = blockIdx.x * blockDim.x + threadIdx.x;
    if (i >= WW_TOTAL) return;
    const float* src; int nc, local;
    if (i < WW_PROJ_OFF)      { src = s0; nc = 3*DIM; local = i - WW_QKV_OFF; }
    else if (i < WW_FC1_OFF)  { src = s1; nc = DIM;   local = i - WW_PROJ_OFF; }
    else if (i < WW_FC2_OFF)  { src = s2; nc = 4*DIM; local = i - WW_FC1_OFF; }
    else                      { src = s3; nc = DIM;   local = i - WW_FC2_OFF; }
    int kp = local / nc, n = local - kp * nc;
    __nv_bfloat16 lo = __float2bfloat16_rn(src[(2*kp    ) * nc + n]);
    __nv_bfloat16 hi = __float2bfloat16_rn(src[(2*kp + 1) * nc + n]);
    g_wh[i] = ((unsigned)__bfloat16_as_ushort(hi) << 16) | __bfloat16_as_ushort(lo);
}

// ---------------- attention bias+mask precompute ----------------
__global__ void prep_bias(const float* __restrict__ btab) {
    int idx = blockIdx.x * 256 + threadIdx.x;
    if (idx >= 4*HEADS*NTOK*NTOK) return;
    int j = idx % NTOK; int r = idx / NTOK;
    int i = r % NTOK;   r /= NTOK;
    int head = r % HEADS;
    int cls  = r / HEADS;
    int cy = cls >> 1, cx = cls & 1;
    int yi = i / WS, xi = i - yi*WS;
    int yj = j / WS, xj = j - yj*WS;
    int rel = (yi - yj + WS - 1) * (2*WS - 1) + (xi - xj + WS - 1);
    float s = btab[rel * HEADS + head];
    int ryi = cy ? ((yi < WS - SHIFT) ? 1 : 2) : 0;
    int rxi = cx ? ((xi < WS - SHIFT) ? 1 : 2) : 0;
    int ryj = cy ? ((yj < WS - SHIFT) ? 1 : 2) : 0;
    int rxj = cx ? ((xj < WS - SHIFT) ? 1 : 2) : 0;
    if (ryi*3 + rxi != ryj*3 + rxj) s -= 100.f;
    g_bt[idx] = s;
}

// ---------------- LayerNorm (bf16 output), optional window-gather ----------------
template<int GATHER>
__global__ void ln_kernel(const float* __restrict__ src, const float* __restrict__ g,
                          const float* __restrict__ bta, __nv_bfloat16* __restrict__ dst) {
    int tok  = blockIdx.x * 8 + (threadIdx.x >> 5);
    int lane = threadIdx.x & 31;
    if (tok >= TTOK) return;
    int srow = GATHER ? win_src_token(tok) : tok;
    const float* p = src + (size_t)srow * DIM;
    float v[6];
    float s = 0.f;
#pragma unroll
    for (int j = 0; j < 6; j++) { v[j] = p[j*32 + lane]; s += v[j]; }
#pragma unroll
    for (int o = 16; o; o >>= 1) s += __shfl_xor_sync(0xffffffffu, s, o);
    float mu = s * (1.f / DIM);
    float vr = 0.f;
#pragma unroll
    for (int j = 0; j < 6; j++) { float d = v[j] - mu; vr += d * d; }
#pragma unroll
    for (int o = 16; o; o >>= 1) vr += __shfl_xor_sync(0xffffffffu, vr, o);
    float r = rsqrtf(vr * (1.f / DIM) + 1e-5f);
    __nv_bfloat16* q = dst + (size_t)tok * DIM;
#pragma unroll
    for (int j = 0; j < 6; j++) {
        int c = j*32 + lane;
        q[c] = __float2bfloat16_rn((v[j] - mu) * r * g[c] + bta[c]);
    }
}

// ---------------- MMA primitives ----------------
__device__ __forceinline__ void mma8(float* c, const unsigned* a, const unsigned* b) {
    asm volatile("mma.sync.aligned.m16n8k8.row.col.f32.tf32.tf32.f32 "
        "{%0,%1,%2,%3},{%4,%5,%6,%7},{%8,%9},{%0,%1,%2,%3};"
        : "+f"(c[0]), "+f"(c[1]), "+f"(c[2]), "+f"(c[3])
        : "r"(a[0]), "r"(a[1]), "r"(a[2]), "r"(a[3]), "r"(b[0]), "r"(b[1]));
}
__device__ __forceinline__ void mma16(float* c, const unsigned* a, const unsigned* b) {
    asm volatile("mma.sync.aligned.m16n8k16.row.col.f32.bf16.bf16.f32 "
        "{%0,%1,%2,%3},{%4,%5,%6,%7},{%8,%9},{%0,%1,%2,%3};"
        : "+f"(c[0]), "+f"(c[1]), "+f"(c[2]), "+f"(c[3])
        : "r"(a[0]), "r"(a[1]), "r"(a[2]), "r"(a[3]), "r"(b[0]), "r"(b[1]));
}

// ---------------- BF16 GEMM, cp.async 3-stage, block 256x64 (R14 core) ----------------
#define AST 12
#define BST 72
#define ASZ (256*AST)
#define BSZ (8*BST)

template<int EPI, int K, int NC>
__global__ __launch_bounds__(256, 2)
void gemm_tc(const __nv_bfloat16* __restrict__ A, const unsigned* __restrict__ Wp,
             const float* __restrict__ bias,
             const float* __restrict__ extra_in,
             float* __restrict__ out, float* __restrict__ out2, float* __restrict__ out3) {
    __shared__ unsigned As[3][ASZ];
    __shared__ unsigned Bs[3][BSZ];

    int t    = threadIdx.x;
    int br   = blockIdx.y * 256;
    int bc   = blockIdx.x * 64;
    int lane = t & 31, warp = t >> 5;
    int wm   = warp & 3, wn = warp >> 2;
    int gid  = lane >> 2, tig = lane & 3;

    const __nv_bfloat16* aRow = A + (size_t)(br + t) * K;
    unsigned aDst = (unsigned)__cvta_generic_to_shared(&As[0][t * AST]);
    int bk = t >> 4, bn4 = (t & 15) * 4;
    unsigned bDst = (unsigned)__cvta_generic_to_shared(&Bs[0][bk * BST + bn4]);

    float acc[4][4][4];
#pragma unroll
    for (int mt = 0; mt < 4; mt++)
#pragma unroll
        for (int nt = 0; nt < 4; nt++)
#pragma unroll
            for (int e = 0; e < 4; e++) acc[mt][nt][e] = 0.f;

    constexpr int KT = K >> 4;

#define ISSUE(S, TI)                                                              \
    do {                                                                          \
        unsigned ad = aDst + (S) * (ASZ * 4);                                     \
        const __nv_bfloat16* ap = aRow + (TI) * 16;                               \
        asm volatile("cp.async.cg.shared.global [%0], [%1], 16;\n"                \
                     :: "r"(ad), "l"(ap) : "memory");                             \
        asm volatile("cp.async.cg.shared.global [%0], [%1], 16;\n"                \
                     :: "r"(ad + 16), "l"(ap + 8) : "memory");                    \
        if (t < 128) {                                                            \
            const unsigned* bp = Wp + (size_t)((TI)*8 + bk) * NC + bc + bn4;      \
            asm volatile("cp.async.cg.shared.global [%0], [%1], 16;\n"            \
                         :: "r"(bDst + (S) * (BSZ * 4)), "l"(bp) : "memory");     \
        }                                                                         \
        asm volatile("cp.async.commit_group;\n" ::: "memory");                    \
    } while (0)

    ISSUE(0, 0);
    ISSUE(1, 1);

    for (int kt = 0; kt < KT; kt++) {
        if (kt < KT - 1) asm volatile("cp.async.wait_group 1;\n" ::: "memory");
        else             asm volatile("cp.async.wait_group 0;\n" ::: "memory");
        __syncthreads();
        int snext = kt + 2;
        if (snext < KT) {
            int sn = snext - (snext / 3) * 3;
            ISSUE(sn, snext);
        }
        int s = kt - (kt / 3) * 3;
        const unsigned* as = As[s];
        const unsigned* bs = Bs[s];

        unsigned a[4][4], b[4][2];
#pragma unroll
        for (int mt = 0; mt < 4; mt++) {
            int rb = wm*64 + mt*16 + gid;
            a[mt][0] = as[ rb      * AST + tig];
            a[mt][1] = as[(rb + 8) * AST + tig];
            a[mt][2] = as[ rb      * AST + tig + 4];
            a[mt][3] = as[(rb + 8) * AST + tig + 4];
        }
#pragma unroll
        for (int nt = 0; nt < 4; nt++) {
            int cb = wn*32 + nt*8 + gid;
            b[nt][0] = bs[ tig      * BST + cb];
            b[nt][1] = bs[(tig + 4) * BST + cb];
        }
#pragma unroll
        for (int mt = 0; mt < 4; mt++)
#pragma unroll
            for (int nt = 0; nt < 4; nt++) mma16(acc[mt][nt], a[mt], b[nt]);
    }
#undef ISSUE

    // epilogue: EPI0 paired (R14); EPI2 paired (this round's delta); EPI1/3 verbatim
#pragma unroll
    for (int mt = 0; mt < 4; mt++) {
#pragma unroll
        for (int rr = 0; rr < 2; rr++) {
            int row = br + wm*64 + mt*16 + gid + rr*8;
            int dst = 0, win = 0, n = 0;
            if (EPI == 0) { win = row / NTOK; n = row - win * NTOK; }
            if (EPI == 1) { dst = win_src_token(row); }
#pragma unroll
            for (int nt = 0; nt < 4; nt++) {
                if (EPI == 0) {
                    int col0 = bc + wn*32 + nt*8 + tig*2;
                    float v0 = acc[mt][nt][rr*2 + 0] + __ldg(&bias[col0]);
                    float v1 = acc[mt][nt][rr*2 + 1] + __ldg(&bias[col0 + 1]);
                    int sseg   = col0 / DIM;
                    int within = col0 % DIM;
                    int hh = within >> 5, d = within & 31;
                    size_t off = (((size_t)(win*HEADS + hh)) * NTOK + n) * HD + d;
                    if (sseg == 0) { v0 *= SCALE; v1 *= SCALE; }
                    __nv_bfloat16* ob = (sseg == 0) ? (__nv_bfloat16*)out
                                      : ((sseg == 1) ? (__nv_bfloat16*)out2
                                                     : (__nv_bfloat16*)out3);
                    __nv_bfloat162 pp = __floats2bfloat162_rn(v0, v1);
                    *(__nv_bfloat162*)(ob + off) = pp;
                } else if (EPI == 2) {
                    int col0 = bc + wn*32 + nt*8 + tig*2;
                    float v0 = acc[mt][nt][rr*2 + 0] + __ldg(&bias[col0]);
                    float v1 = acc[mt][nt][rr*2 + 1] + __ldg(&bias[col0 + 1]);
                    v0 = 0.5f * v0 * (1.f + erff(v0 * 0.70710678118654752f));
                    v1 = 0.5f * v1 * (1.f + erff(v1 * 0.70710678118654752f));
                    __nv_bfloat162 pp = __floats2bfloat162_rn(v0, v1);
                    *(__nv_bfloat162*)((__nv_bfloat16*)out + (size_t)row * (4*DIM) + col0) = pp;
                } else {
#pragma unroll
                    for (int cc = 0; cc < 2; cc++) {
                        int col = bc + wn*32 + nt*8 + tig*2 + cc;
                        float val = acc[mt][nt][rr*2 + cc] + __ldg(&bias[col]);
                        if (EPI == 1) {
                            size_t off = (size_t)dst * DIM + col;
                            out[off] = extra_in[off] + val;
                        } else {
                            size_t off = (size_t)row * DIM + col;
                            out[off] = val + extra_in[off];
                        }
                    }
                }
            }
        }
    }
}

// ---------------- attention: QK on bf16 mma16 (delta); rest R14 verbatim --------------
// qs/ks: bf16 pair-words [row][16] stride 20 (banks 20*gid+tig distinct -> conflict-free).
// vsm: fp32 [56][40] unpacked (R14 layout).
__global__ __launch_bounds__(128, 6)
void attn_kernel() {
    int bh   = blockIdx.x;
    int win  = bh / HEADS;
    int head = bh - win * HEADS;

    __shared__ unsigned qs [64][20];
    __shared__ unsigned ks [56][20];
    __shared__ float    vsm[56][40];

    const unsigned* qp32 = (const unsigned*)(g_q + (size_t)bh * (NTOK*HD));
    const unsigned* kp32 = (const unsigned*)(g_k + (size_t)bh * (NTOK*HD));
    const unsigned* vp32 = (const unsigned*)(g_v + (size_t)bh * (NTOK*HD));

    int t = threadIdx.x;
    if (t < 224) vsm[NTOK + (t >> 5)][t & 31] = 0.f;
    // stage q/k as bf16 pair-words (direct copy); v unpacked to fp32
    for (int i = t; i < NTOK*16; i += 128) {
        int r = i >> 4, w = i & 15;
        qs[r][w] = qp32[i];
        ks[r][w] = kp32[i];
        float2 fv = __bfloat1622float2(*(const __nv_bfloat162*)&vp32[i]);
        vsm[r][w*2] = fv.x; vsm[r][w*2 + 1] = fv.y;
    }
    // zero q/k pad rows (q rows 49..63 feed masked scores; keep finite)
    for (int i = t; i < (64 - NTOK)*16; i += 128) {
        int r = NTOK + (i >> 4), w = i & 15;
        qs[r][w] = 0u;
        if (r < 56) ks[r][w] = 0u;
    }
    __syncthreads();

    int lane = t & 31, warp = t >> 5;
    int gid  = lane >> 2, tig = lane & 3;
    int row0 = warp * 16 + gid;
    int row_lo = row0, row_hi = row0 + 8;

    // ---- S = Q @ K^T : 2 x k16 bf16 MMA (was 4 x k8 tf32) ----
    float acc[7][4];
#pragma unroll
    for (int nt = 0; nt < 7; nt++)
#pragma unroll
        for (int e = 0; e < 4; e++) acc[nt][e] = 0.f;

#pragma unroll
    for (int kt = 0; kt < 2; kt++) {
        unsigned a[4];
        a[0] = qs[row_lo][kt*8 + tig];
        a[1] = qs[row_hi][kt*8 + tig];
        a[2] = qs[row_lo][kt*8 + tig + 4];
        a[3] = qs[row_hi][kt*8 + tig + 4];
#pragma unroll
        for (int nt = 0; nt < 7; nt++) {
            unsigned b[2];
            b[0] = ks[nt*8 + gid][kt*8 + tig];
            b[1] = ks[nt*8 + gid][kt*8 + tig + 4];
            mma16(acc[nt], a, b);
        }
    }

    // bias + shift mask via precomputed class table
    int wi = win & 63;
    int cls = (((wi >> 3) == 7) ? 2 : 0) | (((wi & 7) == 7) ? 1 : 0);
    const float* tb = g_bt + ((size_t)(cls * HEADS + head)) * (NTOK*NTOK);
#pragma unroll
    for (int nt = 0; nt < 7; nt++) {
#pragma unroll
        for (int e = 0; e < 4; e++) {
            int i = (e >= 2) ? row_hi : row_lo;
            int j = nt*8 + tig*2 + (e & 1);
            if (i < NTOK && j < NTOK)
                acc[nt][e] += __ldg(&tb[i * NTOK + j]);
            else
                acc[nt][e] = -1e30f;
        }
    }

    float m0 = -1e30f, m1 = -1e30f;
#pragma unroll
    for (int nt = 0; nt < 7; nt++) {
        m0 = fmaxf(m0, fmaxf(acc[nt][0], acc[nt][1]));
        m1 = fmaxf(m1, fmaxf(acc[nt][2], acc[nt][3]));
    }
    m0 = fmaxf(m0, __shfl_xor_sync(0xffffffffu, m0, 1));
    m0 = fmaxf(m0, __shfl_xor_sync(0xffffffffu, m0, 2));
    m1 = fmaxf(m1, __shfl_xor_sync(0xffffffffu, m1, 1));
    m1 = fmaxf(m1, __shfl_xor_sync(0xffffffffu, m1, 2));
    float s0 = 0.f, s1 = 0.f;
#pragma unroll
    for (int nt = 0; nt < 7; nt++) {
        acc[nt][0] = __expf(acc[nt][0] - m0); s0 += acc[nt][0];
        acc[nt][1] = __expf(acc[nt][1] - m0); s0 += acc[nt][1];
        acc[nt][2] = __expf(acc[nt][2] - m1); s1 += acc[nt][2];
        acc[nt][3] = __expf(acc[nt][3] - m1); s1 += acc[nt][3];
    }
    s0 += __shfl_xor_sync(0xffffffffu, s0, 1);
    s0 += __shfl_xor_sync(0xffffffffu, s0, 2);
    s1 += __shfl_xor_sync(0xffffffffu, s1, 1);
    s1 += __shfl_xor_sync(0xffffffffu, s1, 2);
    float inv0 = 1.f / s0, inv1 = 1.f / s1;
#pragma unroll
    for (int nt = 0; nt < 7; nt++) {
        acc[nt][0] *= inv0; acc[nt][1] *= inv0;
        acc[nt][2] *= inv1; acc[nt][3] *= inv1;
    }

    // ---- O = P @ V (tf32 + shfl permute, R14 verbatim) ----
    float oacc[4][4];
#pragma unroll
    for (int nt = 0; nt < 4; nt++)
#pragma unroll
        for (int e = 0; e < 4; e++) oacc[nt][e] = 0.f;

    int base = lane & ~3;
    int sl0  = base + (tig >> 1);
    int sl1  = sl0 + 2;
    int odd  = tig & 1;

#pragma unroll
    for (int k7 = 0; k7 < 7; k7++) {
        float x0 = acc[k7][0], x1 = acc[k7][1];
        float y0 = acc[k7][2], y1 = acc[k7][3];
        float t0, t1;
        unsigned a[4];
        t0 = __shfl_sync(0xffffffffu, x0, sl0);
        t1 = __shfl_sync(0xffffffffu, x1, sl0);
        a[0] = __float_as_uint(odd ? t1 : t0);
        t0 = __shfl_sync(0xffffffffu, y0, sl0);
        t1 = __shfl_sync(0xffffffffu, y1, sl0);
        a[1] = __float_as_uint(odd ? t1 : t0);
        t0 = __shfl_sync(0xffffffffu, x0, sl1);
        t1 = __shfl_sync(0xffffffffu, x1, sl1);
        a[2] = __float_as_uint(odd ? t1 : t0);
        t0 = __shfl_sync(0xffffffffu, y0, sl1);
        t1 = __shfl_sync(0xffffffffu, y1, sl1);
        a[3] = __float_as_uint(odd ? t1 : t0);

        int kk = k7*8 + tig;
#pragma unroll
        for (int nt = 0; nt < 4; nt++) {
            unsigned b[2];
            b[0] = __float_as_uint(vsm[kk    ][nt*8 + gid]);
            b[1] = __float_as_uint(vsm[kk + 4][nt*8 + gid]);
            mma8(oacc[nt], a, b);
        }
    }

    __nv_bfloat16* op = g_ao + ((size_t)win * NTOK) * DIM + head * HD;
#pragma unroll
    for (int nt = 0; nt < 4; nt++) {
#pragma unroll
        for (int e = 0; e < 4; e++) {
            int i = (e >= 2) ? row_hi : row_lo;
            int d = nt*8 + tig*2 + (e & 1);
            if (i < NTOK) op[(size_t)i * DIM + d] = __float2bfloat16_rn(oacc[nt][e]);
        }
    }
}

// ---------------- launch ----------------
static void* sym_ptr_raw(const void* sym) {
    void* p = nullptr;
    cudaGetSymbolAddress(&p, sym);
    return p;
}

extern "C" void kernel_launch(void* const* d_in, const int* in_sizes, int n_in,
                              void* d_out, int out_size) {
    const float* x       = (const float*)d_in[0];
    const float* n1g     = (const float*)d_in[1];
    const float* n1b     = (const float*)d_in[2];
    const float* qkv_w   = (const float*)d_in[3];
    const float* qkv_b   = (const float*)d_in[4];
    const float* proj_w  = (const float*)d_in[5];
    const float* proj_b  = (const float*)d_in[6];
    const float* btab    = (const float*)d_in[7];
    const float* n2g     = (const float*)d_in[8];
    const float* n2b     = (const float*)d_in[9];
    const float* fc1_w   = (const float*)d_in[10];
    const float* fc1_b   = (const float*)d_in[11];
    const float* fc2_w   = (const float*)d_in[12];
    const float* fc2_b   = (const float*)d_in[13];
    float* outp = (float*)d_out;

    __nv_bfloat16* hln = (__nv_bfloat16*)sym_ptr_raw(g_hln);
    __nv_bfloat16* q   = (__nv_bfloat16*)sym_ptr_raw(g_q);
    __nv_bfloat16* k   = (__nv_bfloat16*)sym_ptr_raw(g_k);
    __nv_bfloat16* v   = (__nv_bfloat16*)sym_ptr_raw(g_v);
    __nv_bfloat16* ao  = (__nv_bfloat16*)sym_ptr_raw(g_ao);
    float*         xn  = (float*)sym_ptr_raw(g_xn);
    __nv_bfloat16* ml  = (__nv_bfloat16*)sym_ptr_raw(g_ml);
    unsigned*      wh  = (unsigned*)sym_ptr_raw(g_wh);

    // 0. prep
    round_w<<<(WW_TOTAL + 255)/256, 256>>>(qkv_w, proj_w, fc1_w, fc2_w);
    prep_bias<<<(4*HEADS*NTOK*NTOK + 255)/256, 256>>>(btab);
    // 1. LN1 + roll + window partition (bf16)
    ln_kernel<1><<<TTOK/8, 256>>>(x, n1g, n1b, hln);
    // 2. qkv GEMM (bf16 out, paired stores)
    gemm_tc<0, DIM, 3*DIM><<<dim3((3*DIM)/64, TTOK/256), 256>>>(hln, wh + WW_QKV_OFF, qkv_b,
                                                                nullptr, (float*)q, (float*)k, (float*)v);
    // 3. windowed attention
    attn_kernel<<<BW*HEADS, 128>>>();
    // 4. proj GEMM + reverse scatter + residual
    gemm_tc<1, DIM, DIM><<<dim3(DIM/64, TTOK/256), 256>>>(ao, wh + WW_PROJ_OFF, proj_b,
                                                          x, xn, nullptr, nullptr);
    // 5. LN2 (bf16 out)
    ln_kernel<0><<<TTOK/8, 256>>>(xn, n2g, n2b, hln);
    // 6. fc1 GEMM + gelu (bf16 out, paired stores)
    gemm_tc<2, DIM, 4*DIM><<<dim3((4*DIM)/64, TTOK/256), 256>>>(hln, wh + WW_FC1_OFF, fc1_b,
                                                                nullptr, (float*)ml, nullptr, nullptr);
    // 7. fc2 GEMM + residual -> output
    gemm_tc<3, 4*DIM, DIM><<<dim3(DIM/64, TTOK/256), 256>>>(ml, wh + WW_FC2_OFF, fc2_b,
                                                            xn, outp, nullptr, nullptr);
}

// round 17
// speedup vs baseline: 1.2751x; 1.0478x over previous
#include <cuda_runtime.h>
#include <cuda_bf16.h>
#include <math.h>

// ---------------- constants ----------------
#define RES   56
#define WS    7
#define SHIFT 3
#define DIM   192
#define HEADS 6
#define HD    32
#define NTOK  49
#define BATCH 32
#define NWIN  64
#define BW    (BATCH*NWIN)        // 2048 windows
#define TTOK  (BW*NTOK)           // 100352 rows
#define SCALE 0.17677669529663687f

#define W_QKV_N    (DIM*3*DIM)
#define W_PROJ_N   (DIM*DIM)
#define W_FC1_N    (DIM*4*DIM)
#define W_FC2_N    (4*DIM*DIM)
#define W_TOTAL    (W_QKV_N + W_PROJ_N + W_FC1_N + W_FC2_N)
#define WW_QKV_OFF  0
#define WW_PROJ_OFF (WW_QKV_OFF + W_QKV_N/2)
#define WW_FC1_OFF  (WW_PROJ_OFF + W_PROJ_N/2)
#define WW_FC2_OFF  (WW_FC1_OFF + W_FC1_N/2)
#define WW_TOTAL    (W_TOTAL/2)

// ---------------- scratch ----------------
__device__ __nv_bfloat16 g_hln[TTOK*DIM];
__device__ __nv_bfloat16 g_q  [TTOK*DIM];
__device__ __nv_bfloat16 g_k  [TTOK*DIM];
__device__ __nv_bfloat16 g_v  [TTOK*DIM];
__device__ __nv_bfloat16 g_ao [TTOK*DIM];
__device__ float         g_xn [TTOK*DIM];
__device__ __nv_bfloat16 g_ml [TTOK*4*DIM];
__device__ unsigned      g_wh [WW_TOTAL];
__device__ float         g_bt [4*HEADS*NTOK*NTOK];

__device__ __forceinline__ int win_src_token(int m) {
    int win = m / NTOK, n = m - win * NTOK;
    int b   = win >> 6, wi = win & 63;
    int wy  = wi >> 3,  wx = wi & 7;
    int py  = n / WS,   px = n - py * WS;
    int y = wy * WS + py + SHIFT; if (y >= RES) y -= RES;
    int x = wx * WS + px + SHIFT; if (x >= RES) x -= RES;
    return b * (RES*RES) + y * RES + x;
}

// ---------------- weight prep ----------------
__global__ void round_w(const float* __restrict__ s0, const float* __restrict__ s1,
                        const float* __restrict__ s2, const float* __restrict__ s3) {
    int i = blockIdx.x * blockDim.x + threadIdx.x;
    if (i >= WW_TOTAL) return;
    const float* src; int nc, local;
    if (i < WW_PROJ_OFF)      { src = s0; nc = 3*DIM; local = i - WW_QKV_OFF; }
    else if (i < WW_FC1_OFF)  { src = s1; nc = DIM;   local = i - WW_PROJ_OFF; }
    else if (i < WW_FC2_OFF)  { src = s2; nc = 4*DIM; local = i - WW_FC1_OFF; }
    else                      { src = s3; nc = DIM;   local = i - WW_FC2_OFF; }
    int kp = local / nc, n = local - kp * nc;
    __nv_bfloat16 lo = __float2bfloat16_rn(src[(2*kp    ) * nc + n]);
    __nv_bfloat16 hi = __float2bfloat16_rn(src[(2*kp + 1) * nc + n]);
    g_wh[i] = ((unsigned)__bfloat16_as_ushort(hi) << 16) | __bfloat16_as_ushort(lo);
}

// ---------------- attention bias+mask precompute ----------------
__global__ void prep_bias(const float* __restrict__ btab) {
    int idx = blockIdx.x * 256 + threadIdx.x;
    if (idx >= 4*HEADS*NTOK*NTOK) return;
    int j = idx % NTOK; int r = idx / NTOK;
    int i = r % NTOK;   r /= NTOK;
    int head = r % HEADS;
    int cls  = r / HEADS;
    int cy = cls >> 1, cx = cls & 1;
    int yi = i / WS, xi = i - yi*WS;
    int yj = j / WS, xj = j - yj*WS;
    int rel = (yi - yj + WS - 1) * (2*WS - 1) + (xi - xj + WS - 1);
    float s = btab[rel * HEADS + head];
    int ryi = cy ? ((yi < WS - SHIFT) ? 1 : 2) : 0;
    int rxi = cx ? ((xi < WS - SHIFT) ? 1 : 2) : 0;
    int ryj = cy ? ((yj < WS - SHIFT) ? 1 : 2) : 0;
    int rxj = cx ? ((xj < WS - SHIFT) ? 1 : 2) : 0;
    if (ryi*3 + rxi != ryj*3 + rxj) s -= 100.f;
    g_bt[idx] = s;
}

// ---------------- LayerNorm ----------------
template<int GATHER>
__global__ void ln_kernel(const float* __restrict__ src, const float* __restrict__ g,
                          const float* __restrict__ bta, __nv_bfloat16* __restrict__ dst) {
    int tok  = blockIdx.x * 8 + (threadIdx.x >> 5);
    int lane = threadIdx.x & 31;
    if (tok >= TTOK) return;
    int srow = GATHER ? win_src_token(tok) : tok;
    const float* p = src + (size_t)srow * DIM;
    float v[6];
    float s = 0.f;
#pragma unroll
    for (int j = 0; j < 6; j++) { v[j] = p[j*32 + lane]; s += v[j]; }
#pragma unroll
    for (int o = 16; o; o >>= 1) s += __shfl_xor_sync(0xffffffffu, s, o);
    float mu = s * (1.f / DIM);
    float vr = 0.f;
#pragma unroll
    for (int j = 0; j < 6; j++) { float d = v[j] - mu; vr += d * d; }
#pragma unroll
    for (int o = 16; o; o >>= 1) vr += __shfl_xor_sync(0xffffffffu, vr, o);
    float r = rsqrtf(vr * (1.f / DIM) + 1e-5f);
    __nv_bfloat16* q = dst + (size_t)tok * DIM;
#pragma unroll
    for (int j = 0; j < 6; j++) {
        int c = j*32 + lane;
        q[c] = __float2bfloat16_rn((v[j] - mu) * r * g[c] + bta[c]);
    }
}

// ---------------- MMA primitives ----------------
__device__ __forceinline__ void mma16(float* c, const unsigned* a, const unsigned* b) {
    asm volatile("mma.sync.aligned.m16n8k16.row.col.f32.bf16.bf16.f32 "
        "{%0,%1,%2,%3},{%4,%5,%6,%7},{%8,%9},{%0,%1,%2,%3};"
        : "+f"(c[0]), "+f"(c[1]), "+f"(c[2]), "+f"(c[3])
        : "r"(a[0]), "r"(a[1]), "r"(a[2]), "r"(a[3]), "r"(b[0]), "r"(b[1]));
}
__device__ __forceinline__ unsigned packbf(float a, float b) {
    __nv_bfloat162 p = __floats2bfloat162_rn(a, b);
    return *(unsigned*)&p;
}

// ---------------- BF16 GEMM, cp.async 3-stage, block 256x64 (R14 core) ----------------
#define AST 12
#define BST 72
#define ASZ (256*AST)
#define BSZ (8*BST)

template<int EPI, int K, int NC>
__global__ __launch_bounds__(256, 2)
void gemm_tc(const __nv_bfloat16* __restrict__ A, const unsigned* __restrict__ Wp,
             const float* __restrict__ bias,
             const float* __restrict__ extra_in,
             float* __restrict__ out, float* __restrict__ out2, float* __restrict__ out3) {
    __shared__ unsigned As[3][ASZ];
    __shared__ unsigned Bs[3][BSZ];

    int t    = threadIdx.x;
    int br   = blockIdx.y * 256;
    int bc   = blockIdx.x * 64;
    int lane = t & 31, warp = t >> 5;
    int wm   = warp & 3, wn = warp >> 2;
    int gid  = lane >> 2, tig = lane & 3;

    const __nv_bfloat16* aRow = A + (size_t)(br + t) * K;
    unsigned aDst = (unsigned)__cvta_generic_to_shared(&As[0][t * AST]);
    int bk = t >> 4, bn4 = (t & 15) * 4;
    unsigned bDst = (unsigned)__cvta_generic_to_shared(&Bs[0][bk * BST + bn4]);

    float acc[4][4][4];
#pragma unroll
    for (int mt = 0; mt < 4; mt++)
#pragma unroll
        for (int nt = 0; nt < 4; nt++)
#pragma unroll
            for (int e = 0; e < 4; e++) acc[mt][nt][e] = 0.f;

    constexpr int KT = K >> 4;

#define ISSUE(S, TI)                                                              \
    do {                                                                          \
        unsigned ad = aDst + (S) * (ASZ * 4);                                     \
        const __nv_bfloat16* ap = aRow + (TI) * 16;                               \
        asm volatile("cp.async.cg.shared.global [%0], [%1], 16;\n"                \
                     :: "r"(ad), "l"(ap) : "memory");                             \
        asm volatile("cp.async.cg.shared.global [%0], [%1], 16;\n"                \
                     :: "r"(ad + 16), "l"(ap + 8) : "memory");                    \
        if (t < 128) {                                                            \
            const unsigned* bp = Wp + (size_t)((TI)*8 + bk) * NC + bc + bn4;      \
            asm volatile("cp.async.cg.shared.global [%0], [%1], 16;\n"            \
                         :: "r"(bDst + (S) * (BSZ * 4)), "l"(bp) : "memory");     \
        }                                                                         \
        asm volatile("cp.async.commit_group;\n" ::: "memory");                    \
    } while (0)

    ISSUE(0, 0);
    ISSUE(1, 1);

    for (int kt = 0; kt < KT; kt++) {
        if (kt < KT - 1) asm volatile("cp.async.wait_group 1;\n" ::: "memory");
        else             asm volatile("cp.async.wait_group 0;\n" ::: "memory");
        __syncthreads();
        int snext = kt + 2;
        if (snext < KT) {
            int sn = snext - (snext / 3) * 3;
            ISSUE(sn, snext);
        }
        int s = kt - (kt / 3) * 3;
        const unsigned* as = As[s];
        const unsigned* bs = Bs[s];

        unsigned a[4][4], b[4][2];
#pragma unroll
        for (int mt = 0; mt < 4; mt++) {
            int rb = wm*64 + mt*16 + gid;
            a[mt][0] = as[ rb      * AST + tig];
            a[mt][1] = as[(rb + 8) * AST + tig];
            a[mt][2] = as[ rb      * AST + tig + 4];
            a[mt][3] = as[(rb + 8) * AST + tig + 4];
        }
#pragma unroll
        for (int nt = 0; nt < 4; nt++) {
            int cb = wn*32 + nt*8 + gid;
            b[nt][0] = bs[ tig      * BST + cb];
            b[nt][1] = bs[(tig + 4) * BST + cb];
        }
#pragma unroll
        for (int mt = 0; mt < 4; mt++)
#pragma unroll
            for (int nt = 0; nt < 4; nt++) mma16(acc[mt][nt], a[mt], b[nt]);
    }
#undef ISSUE

    // epilogue: EPI0/EPI2 paired bf16x2 (validated); EPI1/EPI3 paired float2 (delta)
#pragma unroll
    for (int mt = 0; mt < 4; mt++) {
#pragma unroll
        for (int rr = 0; rr < 2; rr++) {
            int row = br + wm*64 + mt*16 + gid + rr*8;
            int dst = 0, win = 0, n = 0;
            if (EPI == 0) { win = row / NTOK; n = row - win * NTOK; }
            if (EPI == 1) { dst = win_src_token(row); }
#pragma unroll
            for (int nt = 0; nt < 4; nt++) {
                int col0 = bc + wn*32 + nt*8 + tig*2;
                float v0 = acc[mt][nt][rr*2 + 0] + __ldg(&bias[col0]);
                float v1 = acc[mt][nt][rr*2 + 1] + __ldg(&bias[col0 + 1]);
                if (EPI == 0) {
                    int sseg   = col0 / DIM;
                    int within = col0 % DIM;
                    int hh = within >> 5, d = within & 31;
                    size_t off = (((size_t)(win*HEADS + hh)) * NTOK + n) * HD + d;
                    if (sseg == 0) { v0 *= SCALE; v1 *= SCALE; }
                    __nv_bfloat16* ob = (sseg == 0) ? (__nv_bfloat16*)out
                                      : ((sseg == 1) ? (__nv_bfloat16*)out2
                                                     : (__nv_bfloat16*)out3);
                    __nv_bfloat162 pp = __floats2bfloat162_rn(v0, v1);
                    *(__nv_bfloat162*)(ob + off) = pp;
                } else if (EPI == 2) {
                    v0 = 0.5f * v0 * (1.f + erff(v0 * 0.70710678118654752f));
                    v1 = 0.5f * v1 * (1.f + erff(v1 * 0.70710678118654752f));
                    __nv_bfloat162 pp = __floats2bfloat162_rn(v0, v1);
                    *(__nv_bfloat162*)((__nv_bfloat16*)out + (size_t)row * (4*DIM) + col0) = pp;
                } else if (EPI == 1) {
                    size_t off = (size_t)dst * DIM + col0;
                    float2 e = *(const float2*)(extra_in + off);
                    float2 w; w.x = v0 + e.x; w.y = v1 + e.y;
                    *(float2*)(out + off) = w;
                } else {
                    size_t off = (size_t)row * DIM + col0;
                    float2 e = *(const float2*)(extra_in + off);
                    float2 w; w.x = v0 + e.x; w.y = v1 + e.y;
                    *(float2*)(out + off) = w;
                }
            }
        }
    }
}

// ---------------- attention: bf16 QK (R16) + bf16 PV via C-frag repack (delta) --------
// qs/ks: bf16 pair-words [row][16] stride 20; vsm: fp32 [64][36] (rows 49..63 zeroed).
__global__ __launch_bounds__(128, 6)
void attn_kernel() {
    int bh   = blockIdx.x;
    int win  = bh / HEADS;
    int head = bh - win * HEADS;

    __shared__ unsigned qs [64][20];
    __shared__ unsigned ks [56][20];
    __shared__ float    vsm[64][36];

    const unsigned* qp32 = (const unsigned*)(g_q + (size_t)bh * (NTOK*HD));
    const unsigned* kp32 = (const unsigned*)(g_k + (size_t)bh * (NTOK*HD));
    const unsigned* vp32 = (const unsigned*)(g_v + (size_t)bh * (NTOK*HD));

    int t = threadIdx.x;
    // zero V pad rows 49..63 (cols 0..35)
    for (int i = t; i < 15*36; i += 128) {
        vsm[NTOK + i / 36][i % 36] = 0.f;
    }
    // stage q/k as bf16 pair-words; v unpacked to fp32
    for (int i = t; i < NTOK*16; i += 128) {
        int r = i >> 4, w = i & 15;
        qs[r][w] = qp32[i];
        ks[r][w] = kp32[i];
        float2 fv = __bfloat1622float2(*(const __nv_bfloat162*)&vp32[i]);
        vsm[r][w*2] = fv.x; vsm[r][w*2 + 1] = fv.y;
    }
    // zero q/k pad rows
    for (int i = t; i < (64 - NTOK)*16; i += 128) {
        int r = NTOK + (i >> 4), w = i & 15;
        qs[r][w] = 0u;
        if (r < 56) ks[r][w] = 0u;
    }
    __syncthreads();

    int lane = t & 31, warp = t >> 5;
    int gid  = lane >> 2, tig = lane & 3;
    int row0 = warp * 16 + gid;
    int row_lo = row0, row_hi = row0 + 8;

    // ---- S = Q @ K^T : 2 x k16 bf16 MMA ----
    float acc[7][4];
#pragma unroll
    for (int nt = 0; nt < 7; nt++)
#pragma unroll
        for (int e = 0; e < 4; e++) acc[nt][e] = 0.f;

#pragma unroll
    for (int kt = 0; kt < 2; kt++) {
        unsigned a[4];
        a[0] = qs[row_lo][kt*8 + tig];
        a[1] = qs[row_hi][kt*8 + tig];
        a[2] = qs[row_lo][kt*8 + tig + 4];
        a[3] = qs[row_hi][kt*8 + tig + 4];
#pragma unroll
        for (int nt = 0; nt < 7; nt++) {
            unsigned b[2];
            b[0] = ks[nt*8 + gid][kt*8 + tig];
            b[1] = ks[nt*8 + gid][kt*8 + tig + 4];
            mma16(acc[nt], a, b);
        }
    }

    // bias + shift mask via precomputed class table
    int wi = win & 63;
    int cls = (((wi >> 3) == 7) ? 2 : 0) | (((wi & 7) == 7) ? 1 : 0);
    const float* tb = g_bt + ((size_t)(cls * HEADS + head)) * (NTOK*NTOK);
#pragma unroll
    for (int nt = 0; nt < 7; nt++) {
#pragma unroll
        for (int e = 0; e < 4; e++) {
            int i = (e >= 2) ? row_hi : row_lo;
            int j = nt*8 + tig*2 + (e & 1);
            if (i < NTOK && j < NTOK)
                acc[nt][e] += __ldg(&tb[i * NTOK + j]);
            else
                acc[nt][e] = -1e30f;
        }
    }

    // softmax in registers
    float m0 = -1e30f, m1 = -1e30f;
#pragma unroll
    for (int nt = 0; nt < 7; nt++) {
        m0 = fmaxf(m0, fmaxf(acc[nt][0], acc[nt][1]));
        m1 = fmaxf(m1, fmaxf(acc[nt][2], acc[nt][3]));
    }
    m0 = fmaxf(m0, __shfl_xor_sync(0xffffffffu, m0, 1));
    m0 = fmaxf(m0, __shfl_xor_sync(0xffffffffu, m0, 2));
    m1 = fmaxf(m1, __shfl_xor_sync(0xffffffffu, m1, 1));
    m1 = fmaxf(m1, __shfl_xor_sync(0xffffffffu, m1, 2));
    float s0 = 0.f, s1 = 0.f;
#pragma unroll
    for (int nt = 0; nt < 7; nt++) {
        acc[nt][0] = __expf(acc[nt][0] - m0); s0 += acc[nt][0];
        acc[nt][1] = __expf(acc[nt][1] - m0); s0 += acc[nt][1];
        acc[nt][2] = __expf(acc[nt][2] - m1); s1 += acc[nt][2];
        acc[nt][3] = __expf(acc[nt][3] - m1); s1 += acc[nt][3];
    }
    s0 += __shfl_xor_sync(0xffffffffu, s0, 1);
    s0 += __shfl_xor_sync(0xffffffffu, s0, 2);
    s1 += __shfl_xor_sync(0xffffffffu, s1, 1);
    s1 += __shfl_xor_sync(0xffffffffu, s1, 2);
    float inv0 = 1.f / s0, inv1 = 1.f / s1;

    // ---- pack P to bf16 pair-words (adjacent C elements ARE the A-frag k-pairs) ----
    unsigned pw[7][2];
#pragma unroll
    for (int nt = 0; nt < 7; nt++) {
        pw[nt][0] = packbf(acc[nt][0] * inv0, acc[nt][1] * inv0);  // row_lo
        pw[nt][1] = packbf(acc[nt][2] * inv1, acc[nt][3] * inv1);  // row_hi
    }

    // ---- O = P @ V : 4 x k16 bf16 MMA, B packed from fp32 vsm on the fly ----
    float oacc[4][4];
#pragma unroll
    for (int nt = 0; nt < 4; nt++)
#pragma unroll
        for (int e = 0; e < 4; e++) oacc[nt][e] = 0.f;

#pragma unroll
    for (int kt = 0; kt < 4; kt++) {
        int ntA = 2*kt, ntB = 2*kt + 1;
        unsigned a[4];
        a[0] = pw[ntA][0];
        a[1] = pw[ntA][1];
        a[2] = (ntB < 7) ? pw[ntB][0] : 0u;
        a[3] = (ntB < 7) ? pw[ntB][1] : 0u;
        int j0 = kt*16 + 2*tig;
#pragma unroll
        for (int nt2 = 0; nt2 < 4; nt2++) {
            int d = nt2*8 + gid;
            unsigned b[2];
            b[0] = packbf(vsm[j0    ][d], vsm[j0 + 1][d]);
            b[1] = packbf(vsm[j0 + 8][d], vsm[j0 + 9][d]);
            mma16(oacc[nt2], a, b);
        }
    }

    __nv_bfloat16* op = g_ao + ((size_t)win * NTOK) * DIM + head * HD;
#pragma unroll
    for (int nt2 = 0; nt2 < 4; nt2++) {
#pragma unroll
        for (int e = 0; e < 4; e++) {
            int i = (e >= 2) ? row_hi : row_lo;
            int d = nt2*8 + tig*2 + (e & 1);
            if (i < NTOK) op[(size_t)i * DIM + d] = __float2bfloat16_rn(oacc[nt2][e]);
        }
    }
}

// ---------------- launch ----------------
static void* sym_ptr_raw(const void* sym) {
    void* p = nullptr;
    cudaGetSymbolAddress(&p, sym);
    return p;
}

extern "C" void kernel_launch(void* const* d_in, const int* in_sizes, int n_in,
                              void* d_out, int out_size) {
    const float* x       = (const float*)d_in[0];
    const float* n1g     = (const float*)d_in[1];
    const float* n1b     = (const float*)d_in[2];
    const float* qkv_w   = (const float*)d_in[3];
    const float* qkv_b   = (const float*)d_in[4];
    const float* proj_w  = (const float*)d_in[5];
    const float* proj_b  = (const float*)d_in[6];
    const float* btab    = (const float*)d_in[7];
    const float* n2g     = (const float*)d_in[8];
    const float* n2b     = (const float*)d_in[9];
    const float* fc1_w   = (const float*)d_in[10];
    const float* fc1_b   = (const float*)d_in[11];
    const float* fc2_w   = (const float*)d_in[12];
    const float* fc2_b   = (const float*)d_in[13];
    float* outp = (float*)d_out;

    __nv_bfloat16* hln = (__nv_bfloat16*)sym_ptr_raw(g_hln);
    __nv_bfloat16* q   = (__nv_bfloat16*)sym_ptr_raw(g_q);
    __nv_bfloat16* k   = (__nv_bfloat16*)sym_ptr_raw(g_k);
    __nv_bfloat16* v   = (__nv_bfloat16*)sym_ptr_raw(g_v);
    __nv_bfloat16* ao  = (__nv_bfloat16*)sym_ptr_raw(g_ao);
    float*         xn  = (float*)sym_ptr_raw(g_xn);
    __nv_bfloat16* ml  = (__nv_bfloat16*)sym_ptr_raw(g_ml);
    unsigned*      wh  = (unsigned*)sym_ptr_raw(g_wh);

    // 0. prep
    round_w<<<(WW_TOTAL + 255)/256, 256>>>(qkv_w, proj_w, fc1_w, fc2_w);
    prep_bias<<<(4*HEADS*NTOK*NTOK + 255)/256, 256>>>(btab);
    // 1. LN1 + roll + window partition (bf16)
    ln_kernel<1><<<TTOK/8, 256>>>(x, n1g, n1b, hln);
    // 2. qkv GEMM (bf16 out, paired stores)
    gemm_tc<0, DIM, 3*DIM><<<dim3((3*DIM)/64, TTOK/256), 256>>>(hln, wh + WW_QKV_OFF, qkv_b,
                                                                nullptr, (float*)q, (float*)k, (float*)v);
    // 3. windowed attention (full bf16 MMA path)
    attn_kernel<<<BW*HEADS, 128>>>();
    // 4. proj GEMM + reverse scatter + residual (paired float2)
    gemm_tc<1, DIM, DIM><<<dim3(DIM/64, TTOK/256), 256>>>(ao, wh + WW_PROJ_OFF, proj_b,
                                                          x, xn, nullptr, nullptr);
    // 5. LN2 (bf16 out)
    ln_kernel<0><<<TTOK/8, 256>>>(xn, n2g, n2b, hln);
    // 6. fc1 GEMM + gelu (bf16 out, paired stores)
    gemm_tc<2, DIM, 4*DIM><<<dim3((4*DIM)/64, TTOK/256), 256>>>(hln, wh + WW_FC1_OFF, fc1_b,
                                                                nullptr, (float*)ml, nullptr, nullptr);
    // 7. fc2 GEMM + residual -> output (paired float2)
    gemm_tc<3, 4*DIM, DIM><<<dim3(DIM/64, TTOK/256), 256>>>(ml, wh + WW_FC2_OFF, fc2_b,
                                                            xn, outp, nullptr, nullptr);
}